// round 16
// baseline (speedup 1.0000x reference)
#include <cuda_runtime.h>
#include <math.h>

typedef unsigned int   u32;
typedef unsigned short u16;
typedef unsigned long long ull;

// ---------------------------------------------------------------------------
// Scratch buffers (device globals — allocation-free per harness rules)
// ---------------------------------------------------------------------------
__device__ float g_a1[18585600];     // conv1 out [64,96,55,55]
__device__ float g_a2[11943936];     // conv2 out [64,256,27,27]
__device__ float g_a5[3211264];      // conv5 out [64,256,14,14]
__device__ float g_pcpart[2359296];  // pc split-K partials; later FC partials
__device__ float g_ut[589824];       // transposed capsules [1152,64,8]
__device__ float g_sp[930816];       // partial s [9,64,101,16]
__device__ float g_bl[7446528];      // b logits [101,1152,64]
__device__ float g_cc[7446528];      // coupling coeffs (unnormalized exp)
__device__ float g_isum[73728];      // softmax reciprocal row sums [1152,64]
__device__ float g_v[103424];        // v [64,101,16]
__device__ float g_f1[262144];       // fc1 out [64,4096]
__device__ float g_f2[262144];       // fc2 out [64,4096]
__device__ u32   g_packA[10000000];  // packed hi|lo activations (ping)
__device__ u32   g_packB[5000000];   // packed hi|lo activations (pong)
__device__ u32   g_packW[4500000];   // fragment-major weights, per-layer regions

// ---------------------------------------------------------------------------
// bf16 hi/lo split: x ≈ hi + lo (both bf16 RNE). packed u32 = (hi<<16)|lo
// ---------------------------------------------------------------------------
__device__ __forceinline__ u32 pack_hilo(float x)
{
    u32 u  = __float_as_uint(x);
    u32 hi = (u + 0x7fffu + ((u >> 16) & 1u)) >> 16;
    float hf = __uint_as_float(hi << 16);
    u32 v  = __float_as_uint(x - hf);
    u32 lo = (v + 0x7fffu + ((v >> 16) & 1u)) >> 16;
    return (hi << 16) | lo;
}

__global__ void pack_act_k(const float* __restrict__ src, u32* __restrict__ dst, int n)
{
    int i = blockIdx.x * blockDim.x + threadIdx.x;
    if (i < n) dst[i] = pack_hilo(src[i]);
}

// ---------------------------------------------------------------------------
// Fragment-major weight pack (A-fragment {a0..a3} = 16 contiguous bytes)
// ---------------------------------------------------------------------------
__global__ void pack_wfrag_k(const float* __restrict__ src,
                             u32* __restrict__ hi, u32* __restrict__ lo,
                             int M, int K, int Kpad, int nstage, int tot)
{
    int o = blockIdx.x * blockDim.x + threadIdx.x;
    if (o >= tot) return;
    int rem = o & 127, blk = o >> 7;
    int lane = rem >> 2, reg = rem & 3;
    int g = lane >> 2, qi = lane & 3;
    int sub = blk & 15, blk2 = blk >> 4;
    int t = sub >> 1, kk = sub & 1;
    int ck = blk2 % nstage, mb = blk2 / nstage;
    int row = mb * 128 + t * 16 + g + (reg & 1) * 8;
    int k0  = ck * 32 + kk * 16 + qi * 2 + (reg >> 1) * 8;
    float x0 = (row < M && k0 < K)     ? src[(long)row * K + k0]     : 0.f;
    float x1 = (row < M && k0 + 1 < K) ? src[(long)row * K + k0 + 1] : 0.f;
    u32 p0 = pack_hilo(x0), p1 = pack_hilo(x1);
    hi[o] = (p0 >> 16) | (p1 & 0xffff0000u);
    lo[o] = (p0 & 0xffffu) | (p1 << 16);
}

// ---------------------------------------------------------------------------
// mma.sync bf16 + cp.async helpers
// ---------------------------------------------------------------------------
__device__ __forceinline__ void mma_bf16(float* d, const u32* a, u32 b0, u32 b1)
{
    asm("mma.sync.aligned.m16n8k16.row.col.f32.bf16.bf16.f32 "
        "{%0,%1,%2,%3}, {%4,%5,%6,%7}, {%8,%9}, {%0,%1,%2,%3};"
        : "+f"(d[0]), "+f"(d[1]), "+f"(d[2]), "+f"(d[3])
        : "r"(a[0]), "r"(a[1]), "r"(a[2]), "r"(a[3]), "r"(b0), "r"(b1));
}

__device__ __forceinline__ void cp_async16(u32 dst, const void* src)
{
    asm volatile("cp.async.ca.shared.global [%0], [%1], 16;"
                 :: "r"(dst), "l"(src) : "memory");
}
__device__ __forceinline__ void cp_commit()
{
    asm volatile("cp.async.commit_group;" ::: "memory");
}
template<int N> __device__ __forceinline__ void cp_wait()
{
    asm volatile("cp.async.wait_group %0;" :: "n"(N) : "memory");
}

// ---------------------------------------------------------------------------
// Implicit-GEMM conv on mma.sync bf16, 2-term split (3 passes).
// v6 = v3 + pass-major MMA ordering: same-acc reuse distance 2 -> 16 MMAs
// (breaks HMMA RAW chains; B hi fragments reloaded per pass — LDS is cheap).
// ---------------------------------------------------------------------------
static constexpr int CV_AH = 0;
static constexpr int CV_AL = 8192;
static constexpr int CV_BH = 16384;
static constexpr int CV_BL = 24576;
static constexpr int CV_STAGE = 32768;
static constexpr int CV_SMEM  = 69632;

template<int KH, int KW, int SS, int PP>
__global__ __launch_bounds__(256)
void convhmma_k(const u32* __restrict__ whi, const u32* __restrict__ wlo,
                const u32* __restrict__ pin, const float* __restrict__ bias,
                void* __restrict__ outv,
                int M, int C, int H, int W, int OH, int OW,
                int K, int Kpad, int relu, int packout, int accum, int nsplit)
{
    extern __shared__ char smem[];
    const u32 sbase = (u32)__cvta_generic_to_shared(smem);

    const int tid  = threadIdx.x;
    const int wid  = tid >> 5, lane = tid & 31;
    const int KHW  = KH * KW;
    const int OHW  = OH * OW;
    const int N    = 64 * OHW;
    const int m0   = blockIdx.y * 128, n0 = blockIdx.x * 128;
    const int mb   = blockIdx.y;
    const int mwarp = (wid >> 1) * 32, nwarp = (wid & 1) * 64;

    const int lrow = tid & 127;
    const int half = tid >> 7;

    const int gn = n0 + lrow;
    const bool nvalid = gn < N;
    const int bn = nvalid ? gn : 0;
    const int ow = bn % OW;
    const int t1 = bn / OW;
    const int oh = t1 % OH;
    const int bb = t1 / OH;
    const int ihb = oh * SS - PP, iwb = ow * SS - PP;
    const u32* inb = pin + (long)bb * C * H * W;

    const int nstage = Kpad / 32;
    const int per = nstage / nsplit;
    const int ck0 = blockIdx.z * per;
    const int ck1 = ck0 + per;

    auto issueA = [&](int ck, int buf) {
        const u32* sh = whi + ((long)(mb * nstage + ck)) * 2048 + tid * 8;
        const u32* sl = wlo + ((long)(mb * nstage + ck)) * 2048 + tid * 8;
        u32 d = sbase + buf * CV_STAGE + tid * 32;
        cp_async16(d + CV_AH,      sh);
        cp_async16(d + CV_AH + 16, sh + 4);
        cp_async16(d + CV_AL,      sl);
        cp_async16(d + CV_AL + 16, sl + 4);
        cp_commit();
    };

    u32 breg[16];
    auto loadB = [&](int ck) {
        int gk0 = ck * 32 + half * 16;
        int cc = gk0 / KHW;
        int r  = gk0 - cc * KHW;
        int kh = r / KW;
        int kw = r - kh * KW;
#pragma unroll
        for (int t = 0; t < 16; t++) {
            u32 v = 0u;
            if (nvalid && gk0 + t < K) {
                int ih = ihb + kh, iw = iwb + kw;
                if ((unsigned)ih < (unsigned)H && (unsigned)iw < (unsigned)W)
                    v = inb[((long)cc * H + ih) * W + iw];
            }
            breg[t] = v;
            if (++kw == KW) { kw = 0; if (++kh == KH) { kh = 0; ++cc; } }
        }
    };
    auto storeB = [&](int buf) {
        u32 h[8], l[8];
#pragma unroll
        for (int qi = 0; qi < 4; qi++) {
            h[2 * qi]     = __byte_perm(breg[2 * qi],     breg[2 * qi + 1], 0x7632);
            h[2 * qi + 1] = __byte_perm(breg[2 * qi + 8], breg[2 * qi + 9], 0x7632);
            l[2 * qi]     = __byte_perm(breg[2 * qi],     breg[2 * qi + 1], 0x5410);
            l[2 * qi + 1] = __byte_perm(breg[2 * qi + 8], breg[2 * qi + 9], 0x5410);
        }
        int ntile = lrow >> 3, gg = lrow & 7;
        char* base = smem + buf * CV_STAGE + (ntile * 2 + half) * 256 + gg * 32;
        *(uint4*)(base + CV_BH)      = make_uint4(h[0], h[1], h[2], h[3]);
        *(uint4*)(base + CV_BH + 16) = make_uint4(h[4], h[5], h[6], h[7]);
        *(uint4*)(base + CV_BL)      = make_uint4(l[0], l[1], l[2], l[3]);
        *(uint4*)(base + CV_BL + 16) = make_uint4(l[4], l[5], l[6], l[7]);
    };

    float acc[2][8][4];
#pragma unroll
    for (int i = 0; i < 2; i++)
#pragma unroll
        for (int j = 0; j < 8; j++)
#pragma unroll
            for (int q = 0; q < 4; q++) acc[i][j][q] = 0.f;

    int buf = 0;
    issueA(ck0, 0);
    loadB(ck0);

    for (int ck = ck0; ck < ck1; ck++) {
        storeB(buf);
        cp_wait<0>();
        __syncthreads();
        if (ck + 1 < ck1) {
            issueA(ck + 1, buf ^ 1);
            loadB(ck + 1);
        }

        const char* st = smem + buf * CV_STAGE;
#pragma unroll
        for (int kk = 0; kk < 2; kk++) {
            uint4 ah[2], al[2];
#pragma unroll
            for (int mt = 0; mt < 2; mt++) {
                int tdx = (wid >> 1) * 2 + mt;
                const char* pA = st + (tdx * 2 + kk) * 512 + lane * 16;
                ah[mt] = *(const uint4*)(pA + CV_AH);
                al[mt] = *(const uint4*)(pA + CV_AL);
            }
            // pass-major MMA ordering: same-acc reuse distance = 16 MMAs
#pragma unroll
            for (int nt = 0; nt < 8; nt++) {
                int blk = ((wid & 1) * 8 + nt) * 2 + kk;
                const char* pB = st + blk * 256 + lane * 8;
                uint2 bh = *(const uint2*)(pB + CV_BH);
                mma_bf16(acc[0][nt], (const u32*)&ah[0], bh.x, bh.y);
                mma_bf16(acc[1][nt], (const u32*)&ah[1], bh.x, bh.y);
            }
#pragma unroll
            for (int nt = 0; nt < 8; nt++) {
                int blk = ((wid & 1) * 8 + nt) * 2 + kk;
                const char* pB = st + blk * 256 + lane * 8;
                uint2 bh = *(const uint2*)(pB + CV_BH);
                mma_bf16(acc[0][nt], (const u32*)&al[0], bh.x, bh.y);
                mma_bf16(acc[1][nt], (const u32*)&al[1], bh.x, bh.y);
            }
#pragma unroll
            for (int nt = 0; nt < 8; nt++) {
                int blk = ((wid & 1) * 8 + nt) * 2 + kk;
                const char* pB = st + blk * 256 + lane * 8;
                uint2 bl = *(const uint2*)(pB + CV_BL);
                mma_bf16(acc[0][nt], (const u32*)&ah[0], bl.x, bl.y);
                mma_bf16(acc[1][nt], (const u32*)&ah[1], bl.x, bl.y);
            }
        }
        buf ^= 1;
    }
    __syncthreads();

    // ---- epilogue: smem-staged transpose -> coalesced n-contiguous writes
    {
        const int g = lane >> 2, qi = lane & 3;
        float* tw = (float*)smem + wid * 2176;   // 32 rows x 68 floats
#pragma unroll
        for (int mt = 0; mt < 2; mt++)
#pragma unroll
            for (int nt = 0; nt < 8; nt++)
#pragma unroll
                for (int q = 0; q < 2; q++) {
                    int ln = nt * 8 + 2 * qi + q;
                    tw[(mt * 16 + g) * 68 + ln]     = acc[mt][nt][q];
                    tw[(mt * 16 + 8 + g) * 68 + ln] = acc[mt][nt][2 + q];
                }
        __syncwarp();

        int nA = n0 + nwarp + lane;
        int nB = nA + 32;
        bool okA = nA < N, okB = nB < N;
        int ncA = okA ? nA : 0, ncB = okB ? nB : 0;
        int bA = ncA / OHW, pA = ncA - bA * OHW;
        int bB = ncB / OHW, pB = ncB - bB * OHW;
        long baseA = (long)bA * M * OHW + pA;
        long baseB = (long)bB * M * OHW + pB;
        long zoff = accum ? (long)blockIdx.z * 64 * M * OHW : 0;

        for (int r = 0; r < 32; r++) {
            int m = m0 + mwarp + r;
            if (m >= M) break;
            float bv = accum ? 0.f : bias[m];
            float vA = tw[r * 68 + lane] + bv;
            float vB = tw[r * 68 + 32 + lane] + bv;
            if (relu && !accum) { vA = fmaxf(vA, 0.f); vB = fmaxf(vB, 0.f); }
            long moff = (long)m * OHW;
            if (packout) {
                u32* outp = (u32*)outv;
                if (okA) outp[baseA + moff] = pack_hilo(vA);
                if (okB) outp[baseB + moff] = pack_hilo(vB);
            } else {
                float* outp = (float*)outv;
                if (okA) outp[zoff + baseA + moff] = vA;
                if (okB) outp[zoff + baseB + moff] = vB;
            }
        }
    }
}

// ---------------------------------------------------------------------------
// 64x64-tile f32x2 GEMM (FC layers), deterministic split-K over grid.z.
// ---------------------------------------------------------------------------
__global__ __launch_bounds__(256, 2) void gemm64_k(
    const float* __restrict__ A, const float* __restrict__ Bm,
    const float* __restrict__ bias, float* __restrict__ Cout,
    int M, int N, int K, int relu, int nsplit)
{
    __shared__ __align__(16) float As[16][64];
    __shared__ __align__(16) float Bs[16][64];

    const int tid = threadIdx.x;
    const int m0 = blockIdx.y * 64, n0 = blockIdx.x * 64;
    const int tx = tid & 15, ty = tid >> 4;
    const int lm = tid & 63;
    const int lk4 = (tid >> 6) * 4;

    const int nblk = K >> 4;
    const int base = nblk / nsplit, rem = nblk % nsplit;
    const int z = blockIdx.z;
    const int sblk = z * base + (z < rem ? z : rem);
    const int myblk = base + (z < rem ? 1 : 0);
    const int klo = sblk << 4, khi = (sblk + myblk) << 4;
    const long zoff = (long)z * M * N;

    ull acc[4][2];
#pragma unroll
    for (int i = 0; i < 4; i++) { acc[i][0] = 0ULL; acc[i][1] = 0ULL; }

    for (int k0 = klo; k0 < khi; k0 += 16) {
        {
            int gm = m0 + lm;
            if (gm < M) {
                float4 av = *(const float4*)&A[(long)gm * K + k0 + lk4];
                As[lk4 + 0][lm] = av.x; As[lk4 + 1][lm] = av.y;
                As[lk4 + 2][lm] = av.z; As[lk4 + 3][lm] = av.w;
            } else {
                As[lk4 + 0][lm] = 0.f; As[lk4 + 1][lm] = 0.f;
                As[lk4 + 2][lm] = 0.f; As[lk4 + 3][lm] = 0.f;
            }
        }
        {
            int gn = n0 + lm;
            if (gn < N) {
                float4 bv = *(const float4*)&Bm[(long)gn * K + k0 + lk4];
                Bs[lk4 + 0][lm] = bv.x; Bs[lk4 + 1][lm] = bv.y;
                Bs[lk4 + 2][lm] = bv.z; Bs[lk4 + 3][lm] = bv.w;
            } else {
                Bs[lk4 + 0][lm] = 0.f; Bs[lk4 + 1][lm] = 0.f;
                Bs[lk4 + 2][lm] = 0.f; Bs[lk4 + 3][lm] = 0.f;
            }
        }
        __syncthreads();
#pragma unroll
        for (int kk = 0; kk < 16; kk++) {
            float4 a4 = *(const float4*)&As[kk][ty * 4];
            ulonglong2 bv = *(const ulonglong2*)&Bs[kk][tx * 4];
            ull bp[2] = {bv.x, bv.y};
            float av[4] = {a4.x, a4.y, a4.z, a4.w};
#pragma unroll
            for (int i = 0; i < 4; i++) {
                ull sa;
                asm("mov.b64 %0, {%1, %1};" : "=l"(sa) : "f"(av[i]));
#pragma unroll
                for (int j = 0; j < 2; j++)
                    asm("fma.rn.f32x2 %0, %1, %2, %0;"
                        : "+l"(acc[i][j]) : "l"(sa), "l"(bp[j]));
            }
        }
        __syncthreads();
    }

#pragma unroll
    for (int i = 0; i < 4; i++) {
        int m = m0 + ty * 4 + i;
        if (m >= M) continue;
        float bv = (nsplit == 1 && bias) ? bias[m] : 0.f;
#pragma unroll
        for (int j = 0; j < 2; j++) {
            float lo, hi;
            asm("mov.b64 {%0, %1}, %2;" : "=f"(lo), "=f"(hi) : "l"(acc[i][j]));
            float v0 = lo + bv, v1 = hi + bv;
            if (relu && nsplit == 1) { if (v0 < 0.f) v0 = 0.f; if (v1 < 0.f) v1 = 0.f; }
            int nA = n0 + tx * 4 + 2 * j, nB = nA + 1;
            if (nA < N) Cout[zoff + (long)nA * M + m] = v0;
            if (nB < N) Cout[zoff + (long)nB * M + m] = v1;
        }
    }
}

// combine FC split-K partials + bias (+relu)
__global__ void fccomb_k(const float* __restrict__ part, const float* __restrict__ bias,
                         float* __restrict__ out, int M, int slice, int ns,
                         int relu, int total)
{
    int i = blockIdx.x * blockDim.x + threadIdx.x;
    if (i >= total) return;
    float s = 0.f;
    for (int z = 0; z < ns; z++) s += part[(long)z * slice + i];
    s += bias[i % M];
    if (relu && s < 0.f) s = 0.f;
    out[i] = s;
}

// ---------------------------------------------------------------------------
// Templated MaxPool (3x3 s2), packed u32 output
// ---------------------------------------------------------------------------
template<int C, int H, int W, int OH, int OW, int PAD>
__global__ void maxpool_k(const float* __restrict__ in, u32* __restrict__ out)
{
    constexpr int TOTAL = 64 * C * OH * OW;
    int idx = blockIdx.x * blockDim.x + threadIdx.x;
    if (idx >= TOTAL) return;
    int ow = idx % OW;
    int t = idx / OW;
    int oh = t % OH; t /= OH;
    int c = t % C;
    int b = t / C;
    const float* p = in + (long)(b * C + c) * H * W;
    float mx = -3.4e38f;
    int h0 = oh * 2 - PAD, w0 = ow * 2 - PAD;
#pragma unroll
    for (int kh = 0; kh < 3; kh++) {
        int ih = h0 + kh;
        if (ih < 0 || ih >= H) continue;
#pragma unroll
        for (int kw = 0; kw < 3; kw++) {
            int iw = w0 + kw;
            if (iw < 0 || iw >= W) continue;
            float v = p[ih * W + iw];
            if (v > mx) mx = v;
        }
    }
    out[idx] = pack_hilo(mx);
}

// ---------------------------------------------------------------------------
// pcfuse: split-K combine + bias + squash + transpose -> ut[i][b][8]
// ---------------------------------------------------------------------------
__global__ void pcfuse_k(const float* __restrict__ part, const float* __restrict__ bias,
                         float* __restrict__ ut)
{
    int idx = blockIdx.x * blockDim.x + threadIdx.x;   // 73728 = b*1152+i
    if (idx >= 73728) return;
    int b = idx / 1152, i = idx - b * 1152;
    long base = (long)b * 9216 + (long)i * 8;
    float vals[8];
    float sq = 0.f;
#pragma unroll
    for (int d = 0; d < 8; d++) {
        long f = base + d;
        int m = (i * 8 + d) / 36;
        float s = part[f] + part[f + 589824] + part[f + 1179648] + part[f + 1769472]
                + bias[m];
        vals[d] = s;
        sq += s * s;
    }
    float sc = (sq / (1.f + sq)) / sqrtf(sq + 1e-8f);
    float4* dst = (float4*)(ut + ((long)i * 64 + b) * 8);
    dst[0] = make_float4(vals[0] * sc, vals[1] * sc, vals[2] * sc, vals[3] * sc);
    dst[1] = make_float4(vals[4] * sc, vals[5] * sc, vals[6] * sc, vals[7] * sc);
}

// ---------------------------------------------------------------------------
// Fused routing — x_hat recomputed on the fly from W (L2-resident) + u.
// ---------------------------------------------------------------------------
static constexpr int FR_SMEM = 16384 * 4 + 4 * 64 * 17 * 4;   // 82944
static constexpr int FU_SMEM = 16384 * 4;                     // 65536

__global__ __launch_bounds__(256) void fr_k(
    const float* __restrict__ Wc, const float* __restrict__ ut,
    const float* __restrict__ cct, const float* __restrict__ isum,
    float* __restrict__ sp)
{
    extern __shared__ float sm[];
    float* Wsm = sm;
    float* red = sm + 16384;
    const int tid = threadIdx.x;
    const int p = blockIdx.x, j = blockIdx.y;
    const int i0 = p * 128;
    const int s = tid >> 6, b = tid & 63;

    const float* wsrc = Wc + ((long)j * 1152 + i0) * 128;
    for (int idx = tid; idx < 16384; idx += 256) {
        int row = idx >> 7, r = idx & 127;
        Wsm[row * 128 + (r & 7) * 16 + (r >> 3)] = wsrc[idx];
    }
    __syncthreads();

    ull accp[8];
#pragma unroll
    for (int op = 0; op < 8; op++) accp[op] = 0ULL;

    for (int k = 0; k < 32; k++) {
        const int il = s + 4 * k;
        const int i = i0 + il;
        const float4* up = (const float4*)(ut + ((long)i * 64 + b) * 8);
        float4 u0 = up[0], u1 = up[1];
        float ud[8] = {u0.x, u0.y, u0.z, u0.w, u1.x, u1.y, u1.z, u1.w};
        float cw;
        if (cct) cw = cct[((long)j * 1152 + i) * 64 + b] * isum[i * 64 + b];
        else     cw = 1.f / 101.f;
        const float* wr = Wsm + il * 128;
        ull xp[8];
#pragma unroll
        for (int op = 0; op < 8; op++) xp[op] = 0ULL;
#pragma unroll
        for (int d = 0; d < 8; d++) {
            ull us;
            asm("mov.b64 %0, {%1, %1};" : "=l"(us) : "f"(ud[d]));
            const ulonglong2* wp2 = (const ulonglong2*)(wr + d * 16);
#pragma unroll
            for (int q = 0; q < 4; q++) {
                ulonglong2 wv = wp2[q];
                asm("fma.rn.f32x2 %0, %1, %2, %0;" : "+l"(xp[2*q])   : "l"(us), "l"(wv.x));
                asm("fma.rn.f32x2 %0, %1, %2, %0;" : "+l"(xp[2*q+1]) : "l"(us), "l"(wv.y));
            }
        }
        ull cws;
        asm("mov.b64 %0, {%1, %1};" : "=l"(cws) : "f"(cw));
#pragma unroll
        for (int op = 0; op < 8; op++)
            asm("fma.rn.f32x2 %0, %1, %2, %0;" : "+l"(accp[op]) : "l"(cws), "l"(xp[op]));
    }

    float* rr = red + (s * 64 + b) * 17;
#pragma unroll
    for (int op = 0; op < 8; op++) {
        float lo, hi;
        asm("mov.b64 {%0, %1}, %2;" : "=f"(lo), "=f"(hi) : "l"(accp[op]));
        rr[2 * op] = lo; rr[2 * op + 1] = hi;
    }
    __syncthreads();
    for (int t = tid; t < 1024; t += 256) {
        int ob = t >> 4, oo = t & 15;
        float sum = red[(ob) * 17 + oo] + red[(64 + ob) * 17 + oo]
                  + red[(128 + ob) * 17 + oo] + red[(192 + ob) * 17 + oo];
        sp[(((long)p * 64 + ob) * 101 + j) * 16 + oo] = sum;
    }
}

__global__ void fs_k(const float* __restrict__ sp, float* __restrict__ vout, int total)
{
    int idx = blockIdx.x * blockDim.x + threadIdx.x;
    if (idx >= total) return;               // 103424
    float sum = 0.f;
#pragma unroll
    for (int p = 0; p < 9; p++) sum += sp[(long)p * 103424 + idx];
    float sq = sum * sum;
#pragma unroll
    for (int off = 8; off > 0; off >>= 1)
        sq += __shfl_xor_sync(0xffffffffu, sq, off, 16);
    float sc = (sq / (1.f + sq)) / sqrtf(sq + 1e-8f);
    vout[idx] = sum * sc;
}

__global__ __launch_bounds__(256) void fu_k(
    const float* __restrict__ Wc, const float* __restrict__ ut,
    const float* __restrict__ v, float* __restrict__ bl, int overwrite)
{
    extern __shared__ float sm[];
    float* Wsm = sm;
    const int tid = threadIdx.x;
    const int p = blockIdx.x, j = blockIdx.y;
    const int i0 = p * 128;
    const int s = tid >> 6, b = tid & 63;

    const float* wsrc = Wc + ((long)j * 1152 + i0) * 128;
    for (int idx = tid; idx < 16384; idx += 256) {
        int row = idx >> 7, r = idx & 127;
        Wsm[row * 128 + (r & 7) * 16 + (r >> 3)] = wsrc[idx];
    }
    __syncthreads();

    ull vp[8];
    const ull* vptr = (const ull*)(v + ((long)b * 101 + j) * 16);
#pragma unroll
    for (int op = 0; op < 8; op++) vp[op] = vptr[op];

    for (int k = 0; k < 32; k++) {
        const int il = s + 4 * k;
        const int i = i0 + il;
        const float4* up = (const float4*)(ut + ((long)i * 64 + b) * 8);
        float4 u0 = up[0], u1 = up[1];
        float ud[8] = {u0.x, u0.y, u0.z, u0.w, u1.x, u1.y, u1.z, u1.w};
        const float* wr = Wsm + il * 128;
        ull xp[8];
#pragma unroll
        for (int op = 0; op < 8; op++) xp[op] = 0ULL;
#pragma unroll
        for (int d = 0; d < 8; d++) {
            ull us;
            asm("mov.b64 %0, {%1, %1};" : "=l"(us) : "f"(ud[d]));
            const ulonglong2* wp2 = (const ulonglong2*)(wr + d * 16);
#pragma unroll
            for (int q = 0; q < 4; q++) {
                ulonglong2 wv = wp2[q];
                asm("fma.rn.f32x2 %0, %1, %2, %0;" : "+l"(xp[2*q])   : "l"(us), "l"(wv.x));
                asm("fma.rn.f32x2 %0, %1, %2, %0;" : "+l"(xp[2*q+1]) : "l"(us), "l"(wv.y));
            }
        }
        ull dp = 0ULL;
#pragma unroll
        for (int op = 0; op < 8; op++)
            asm("fma.rn.f32x2 %0, %1, %2, %0;" : "+l"(dp) : "l"(vp[op]), "l"(xp[op]));
        float lo, hi;
        asm("mov.b64 {%0, %1}, %2;" : "=f"(lo), "=f"(hi) : "l"(dp));
        float d = lo + hi;
        long addr = ((long)j * 1152 + i) * 64 + b;
        bl[addr] = overwrite ? d : bl[addr] + d;
    }
}

// softmax over j; layout [101][1152][64]. 2-pass: store unnormalized exp + 1/sum.
__global__ void softmax_t_k(const float* __restrict__ bl, float* __restrict__ cct,
                            float* __restrict__ isum, int total)
{
    int idx = blockIdx.x * blockDim.x + threadIdx.x;
    if (idx >= total) return;    // 73728
    const float* p = bl + idx;
    float mx = p[0];
    for (int j = 1; j < 101; j++) {
        float t = p[(long)j * 73728];
        if (t > mx) mx = t;
    }
    float* q = cct + idx;
    float sum = 0.f;
    for (int j = 0; j < 101; j++) {
        float e = __expf(p[(long)j * 73728] - mx);
        q[(long)j * 73728] = e;
        sum += e;
    }
    isum[idx] = 1.f / sum;
}

// ---------------------------------------------------------------------------
// Host-side orchestration
// ---------------------------------------------------------------------------
static float* symaddr(const void* sym)
{
    void* p = nullptr;
    cudaGetSymbolAddress(&p, sym);
    return (float*)p;
}

struct WReg { int Mpad, Kpad, nstage; u32 *whi, *wlo; };

static WReg wreg(u32* base, size_t off, int M, int K)
{
    WReg r;
    r.Kpad = ((K + 31) / 32) * 32;
    r.Mpad = ((M + 127) / 128) * 128;
    r.nstage = r.Kpad / 32;
    r.whi = base + off;
    r.wlo = r.whi + (size_t)r.Mpad * r.Kpad / 2;
    return r;
}

static void run_packw(const float* w, const WReg& r, int M, int K)
{
    int tot = r.Mpad * r.Kpad / 2;
    pack_wfrag_k<<<(tot + 255) / 256, 256>>>(w, r.whi, r.wlo, M, K, r.Kpad, r.nstage, tot);
}

template<int KH, int KW, int SS, int PP>
static void run_conv(const WReg& r, const u32* pin, const float* bias, void* outv,
                     int M, int C, int H, int Win, int OH, int OW, int relu,
                     int packout, int accum, int nsplit)
{
    const int K = C * KH * KW;
    static bool attr11 = false, attr5 = false, attr3 = false;
    bool& flag = (KH == 11) ? attr11 : (KH == 5) ? attr5 : attr3;
    if (!flag) {
        cudaFuncSetAttribute(convhmma_k<KH, KW, SS, PP>,
                             cudaFuncAttributeMaxDynamicSharedMemorySize, CV_SMEM);
        flag = true;
    }
    int N = 64 * OH * OW;
    dim3 grid((N + 127) / 128, r.Mpad / 128, nsplit);
    convhmma_k<KH, KW, SS, PP><<<grid, 256, CV_SMEM>>>(r.whi, r.wlo, pin, bias, outv,
                                                       M, C, H, Win, OH, OW, K, r.Kpad,
                                                       relu, packout, accum, nsplit);
}

static void run_fc(const float* A, const float* Bm, const float* bias,
                   float* part, float* Cout, int M, int N, int K, int relu, int nsplit)
{
    dim3 grid((N + 63) / 64, (M + 63) / 64, nsplit);
    if (nsplit == 1) {
        gemm64_k<<<grid, 256>>>(A, Bm, bias, Cout, M, N, K, relu, 1);
    } else {
        gemm64_k<<<grid, 256>>>(A, Bm, nullptr, part, M, N, K, 0, nsplit);
        int total = M * N;
        fccomb_k<<<(total + 255) / 256, 256>>>(part, bias, Cout, M, M * N, nsplit,
                                               relu, total);
    }
}

extern "C" void kernel_launch(void* const* d_in, const int* in_sizes, int n_in,
                              void* d_out, int out_size)
{
    const float* x      = (const float*)d_in[0];
    const float* w1     = (const float*)d_in[1];
    const float* b1     = (const float*)d_in[2];
    const float* w2     = (const float*)d_in[3];
    const float* b2     = (const float*)d_in[4];
    const float* w3     = (const float*)d_in[5];
    const float* b3     = (const float*)d_in[6];
    const float* w4     = (const float*)d_in[7];
    const float* b4     = (const float*)d_in[8];
    const float* w5     = (const float*)d_in[9];
    const float* b5     = (const float*)d_in[10];
    const float* pc_w   = (const float*)d_in[11];
    const float* pc_b   = (const float*)d_in[12];
    const float* caps_W = (const float*)d_in[13];
    const float* fc1_w  = (const float*)d_in[14];
    const float* fc1_b  = (const float*)d_in[15];
    const float* fc2_w  = (const float*)d_in[16];
    const float* fc2_b  = (const float*)d_in[17];
    const float* fc3_w  = (const float*)d_in[18];
    const float* fc3_b  = (const float*)d_in[19];
    float* out = (float*)d_out;

    float* a1  = symaddr(g_a1);
    float* a2  = symaddr(g_a2);
    float* a5  = symaddr(g_a5);
    float* pcp = symaddr(g_pcpart);
    float* ut  = symaddr(g_ut);
    float* sp  = symaddr(g_sp);
    float* bl  = symaddr(g_bl);
    float* cc  = symaddr(g_cc);
    float* is  = symaddr(g_isum);
    float* v   = symaddr(g_v);
    float* f1  = symaddr(g_f1);
    float* f2  = symaddr(g_f2);
    u32* bufA = (u32*)symaddr(g_packA);
    u32* bufB = (u32*)symaddr(g_packB);
    u32* pw   = (u32*)symaddr(g_packW);

    // per-layer weight regions (fragment-major, hi+lo)
    WReg r1 = wreg(pw, 0,       96,  3 * 121);
    WReg r2 = wreg(pw, 49152,   256, 96 * 25);
    WReg r3 = wreg(pw, 663552,  384, 256 * 9);
    WReg r4 = wreg(pw, 1548288, 384, 384 * 9);
    WReg r5 = wreg(pw, 2875392, 256, 384 * 9);
    WReg rp = wreg(pw, 3760128, 256, 256 * 9);

    // ---- conv stack ----
    run_packw(w1, r1, 96, 3 * 121);
    run_packw(w2, r2, 256, 96 * 25);
    {
        int tot = 64 * 3 * 227 * 227;
        pack_act_k<<<(tot + 255) / 256, 256>>>(x, bufA, tot);
    }
    run_conv<11, 11, 4, 0>(r1, bufA, b1, a1, 96, 3, 227, 227, 55, 55, 1, 0, 0, 1);
    maxpool_k<96, 55, 55, 27, 27, 0><<<(64 * 96 * 27 * 27 + 255) / 256, 256>>>(a1, bufA);

    run_conv<5, 5, 1, 2>(r2, bufA, b2, a2, 256, 96, 27, 27, 27, 27, 1, 0, 0, 1);
    maxpool_k<256, 27, 27, 14, 14, 1><<<(64 * 256 * 14 * 14 + 255) / 256, 256>>>(a2, bufA);

    run_packw(w3, r3, 384, 256 * 9);
    run_conv<3, 3, 1, 1>(r3, bufA, b3, bufB, 384, 256, 14, 14, 14, 14, 1, 1, 0, 1);
    run_packw(w4, r4, 384, 384 * 9);
    run_conv<3, 3, 1, 1>(r4, bufB, b4, bufA, 384, 384, 14, 14, 14, 14, 1, 1, 0, 1);
    run_packw(w5, r5, 256, 384 * 9);
    run_conv<3, 3, 1, 1>(r5, bufA, b5, a5, 256, 384, 14, 14, 14, 14, 1, 0, 0, 1);
    maxpool_k<256, 14, 14, 6, 6, 0><<<(64 * 256 * 6 * 6 + 255) / 256, 256>>>(a5, bufA);

    // ---- PrimaryCaps conv: split-K x4 + fused combine/squash/transpose ----
    run_packw(pc_w, rp, 256, 256 * 9);
    run_conv<3, 3, 1, 1>(rp, bufA, pc_b, pcp, 256, 256, 6, 6, 6, 6, 0, 0, 1, 4);
    pcfuse_k<<<(73728 + 255) / 256, 256>>>(pcp, pc_b, ut);

    // ---- fused dynamic routing ----
    {
        static bool attrr = false;
        if (!attrr) {
            cudaFuncSetAttribute(fr_k, cudaFuncAttributeMaxDynamicSharedMemorySize, FR_SMEM);
            cudaFuncSetAttribute(fu_k, cudaFuncAttributeMaxDynamicSharedMemorySize, FU_SMEM);
            attrr = true;
        }
        dim3 rg(9, 101);
        fr_k<<<rg, 256, FR_SMEM>>>(caps_W, ut, nullptr, nullptr, sp);
        fs_k<<<404, 256>>>(sp, v, 103424);
        fu_k<<<rg, 256, FU_SMEM>>>(caps_W, ut, v, bl, 1);
        softmax_t_k<<<288, 256>>>(bl, cc, is, 73728);
        fr_k<<<rg, 256, FR_SMEM>>>(caps_W, ut, cc, is, sp);
        fs_k<<<404, 256>>>(sp, v, 103424);
        fu_k<<<rg, 256, FU_SMEM>>>(caps_W, ut, v, bl, 0);
        softmax_t_k<<<288, 256>>>(bl, cc, is, 73728);
        fr_k<<<rg, 256, FR_SMEM>>>(caps_W, ut, cc, is, sp);
        fs_k<<<404, 256>>>(sp, v, 103424);
    }

    // ---- MLP head (deterministic split-K, partials in pcp) ----
    run_fc(fc1_w, v, fc1_b, pcp, f1, 4096, 64, 1616, 1, 4);
    run_fc(fc2_w, f1, fc2_b, pcp, f2, 4096, 64, 4096, 1, 4);
    run_fc(fc3_w, f2, fc3_b, pcp, out, 101, 64, 4096, 0, 16);
}

// round 17
// speedup vs baseline: 1.2656x; 1.2656x over previous
#include <cuda_runtime.h>
#include <math.h>

typedef unsigned int   u32;
typedef unsigned short u16;
typedef unsigned long long ull;

// ---------------------------------------------------------------------------
// Scratch buffers (device globals — allocation-free per harness rules)
// ---------------------------------------------------------------------------
__device__ float g_a1[18585600];     // conv1 out [64,96,55,55]
__device__ float g_a2[11943936];     // conv2 out [64,256,27,27]
__device__ float g_a5[3211264];      // conv5 out [64,256,14,14]
__device__ float g_pcpart[2359296];  // pc partials; routing sp; FC partials
__device__ float g_ut[589824];       // transposed capsules [1152,64,8]
__device__ float g_bl[7446528];      // b logits [101,1152,64]
__device__ float g_cc[7446528];      // coupling coeffs (unnormalized exp)
__device__ float g_isum[73728];      // softmax reciprocal row sums [1152,64]
__device__ float g_v[103424];        // v [64,101,16]
__device__ float g_f1[262144];       // fc1 out [64,4096]
__device__ float g_f2[262144];       // fc2 out [64,4096]
__device__ u32   g_packA[10000000];  // packed hi|lo activations (ping)
__device__ u32   g_packB[5000000];   // packed hi|lo activations (pong)
__device__ u32   g_packW[4500000];   // fragment-major weights, per-layer regions

// ---------------------------------------------------------------------------
// bf16 hi/lo split: x ≈ hi + lo (both bf16 RNE). packed u32 = (hi<<16)|lo
// ---------------------------------------------------------------------------
__device__ __forceinline__ u32 pack_hilo(float x)
{
    u32 u  = __float_as_uint(x);
    u32 hi = (u + 0x7fffu + ((u >> 16) & 1u)) >> 16;
    float hf = __uint_as_float(hi << 16);
    u32 v  = __float_as_uint(x - hf);
    u32 lo = (v + 0x7fffu + ((v >> 16) & 1u)) >> 16;
    return (hi << 16) | lo;
}

__global__ void pack_act_k(const float* __restrict__ src, u32* __restrict__ dst, int n)
{
    int i = blockIdx.x * blockDim.x + threadIdx.x;
    if (i < n) dst[i] = pack_hilo(src[i]);
}

// ---------------------------------------------------------------------------
// Fragment-major weight pack (A-fragment {a0..a3} = 16 contiguous bytes)
// ---------------------------------------------------------------------------
__global__ void pack_wfrag_k(const float* __restrict__ src,
                             u32* __restrict__ hi, u32* __restrict__ lo,
                             int M, int K, int Kpad, int nstage, int tot)
{
    int o = blockIdx.x * blockDim.x + threadIdx.x;
    if (o >= tot) return;
    int rem = o & 127, blk = o >> 7;
    int lane = rem >> 2, reg = rem & 3;
    int g = lane >> 2, qi = lane & 3;
    int sub = blk & 15, blk2 = blk >> 4;
    int t = sub >> 1, kk = sub & 1;
    int ck = blk2 % nstage, mb = blk2 / nstage;
    int row = mb * 128 + t * 16 + g + (reg & 1) * 8;
    int k0  = ck * 32 + kk * 16 + qi * 2 + (reg >> 1) * 8;
    float x0 = (row < M && k0 < K)     ? src[(long)row * K + k0]     : 0.f;
    float x1 = (row < M && k0 + 1 < K) ? src[(long)row * K + k0 + 1] : 0.f;
    u32 p0 = pack_hilo(x0), p1 = pack_hilo(x1);
    hi[o] = (p0 >> 16) | (p1 & 0xffff0000u);
    lo[o] = (p0 & 0xffffu) | (p1 << 16);
}

// ---------------------------------------------------------------------------
// mma.sync bf16 + cp.async helpers
// ---------------------------------------------------------------------------
__device__ __forceinline__ void mma_bf16(float* d, const u32* a, u32 b0, u32 b1)
{
    asm("mma.sync.aligned.m16n8k16.row.col.f32.bf16.bf16.f32 "
        "{%0,%1,%2,%3}, {%4,%5,%6,%7}, {%8,%9}, {%0,%1,%2,%3};"
        : "+f"(d[0]), "+f"(d[1]), "+f"(d[2]), "+f"(d[3])
        : "r"(a[0]), "r"(a[1]), "r"(a[2]), "r"(a[3]), "r"(b0), "r"(b1));
}

__device__ __forceinline__ void cp_async16(u32 dst, const void* src)
{
    asm volatile("cp.async.ca.shared.global [%0], [%1], 16;"
                 :: "r"(dst), "l"(src) : "memory");
}
__device__ __forceinline__ void cp_commit()
{
    asm volatile("cp.async.commit_group;" ::: "memory");
}
template<int N> __device__ __forceinline__ void cp_wait()
{
    asm volatile("cp.async.wait_group %0;" :: "n"(N) : "memory");
}

// ---------------------------------------------------------------------------
// Implicit-GEMM conv on mma.sync bf16, 2-term split (3 passes).
// v3 champion (FROZEN): fragment-major A (cp.async) + register-staged B.
// ---------------------------------------------------------------------------
static constexpr int CV_AH = 0;
static constexpr int CV_AL = 8192;
static constexpr int CV_BH = 16384;
static constexpr int CV_BL = 24576;
static constexpr int CV_STAGE = 32768;
static constexpr int CV_SMEM  = 69632;

template<int KH, int KW, int SS, int PP>
__global__ __launch_bounds__(256)
void convhmma_k(const u32* __restrict__ whi, const u32* __restrict__ wlo,
                const u32* __restrict__ pin, const float* __restrict__ bias,
                void* __restrict__ outv,
                int M, int C, int H, int W, int OH, int OW,
                int K, int Kpad, int relu, int packout, int accum, int nsplit)
{
    extern __shared__ char smem[];
    const u32 sbase = (u32)__cvta_generic_to_shared(smem);

    const int tid  = threadIdx.x;
    const int wid  = tid >> 5, lane = tid & 31;
    const int KHW  = KH * KW;
    const int OHW  = OH * OW;
    const int N    = 64 * OHW;
    const int m0   = blockIdx.y * 128, n0 = blockIdx.x * 128;
    const int mb   = blockIdx.y;
    const int mwarp = (wid >> 1) * 32, nwarp = (wid & 1) * 64;

    const int lrow = tid & 127;
    const int half = tid >> 7;

    const int gn = n0 + lrow;
    const bool nvalid = gn < N;
    const int bn = nvalid ? gn : 0;
    const int ow = bn % OW;
    const int t1 = bn / OW;
    const int oh = t1 % OH;
    const int bb = t1 / OH;
    const int ihb = oh * SS - PP, iwb = ow * SS - PP;
    const u32* inb = pin + (long)bb * C * H * W;

    const int nstage = Kpad / 32;
    const int per = nstage / nsplit;
    const int ck0 = blockIdx.z * per;
    const int ck1 = ck0 + per;

    auto issueA = [&](int ck, int buf) {
        const u32* sh = whi + ((long)(mb * nstage + ck)) * 2048 + tid * 8;
        const u32* sl = wlo + ((long)(mb * nstage + ck)) * 2048 + tid * 8;
        u32 d = sbase + buf * CV_STAGE + tid * 32;
        cp_async16(d + CV_AH,      sh);
        cp_async16(d + CV_AH + 16, sh + 4);
        cp_async16(d + CV_AL,      sl);
        cp_async16(d + CV_AL + 16, sl + 4);
        cp_commit();
    };

    u32 breg[16];
    auto loadB = [&](int ck) {
        int gk0 = ck * 32 + half * 16;
        int cc = gk0 / KHW;
        int r  = gk0 - cc * KHW;
        int kh = r / KW;
        int kw = r - kh * KW;
#pragma unroll
        for (int t = 0; t < 16; t++) {
            u32 v = 0u;
            if (nvalid && gk0 + t < K) {
                int ih = ihb + kh, iw = iwb + kw;
                if ((unsigned)ih < (unsigned)H && (unsigned)iw < (unsigned)W)
                    v = inb[((long)cc * H + ih) * W + iw];
            }
            breg[t] = v;
            if (++kw == KW) { kw = 0; if (++kh == KH) { kh = 0; ++cc; } }
        }
    };
    auto storeB = [&](int buf) {
        u32 h[8], l[8];
#pragma unroll
        for (int qi = 0; qi < 4; qi++) {
            h[2 * qi]     = __byte_perm(breg[2 * qi],     breg[2 * qi + 1], 0x7632);
            h[2 * qi + 1] = __byte_perm(breg[2 * qi + 8], breg[2 * qi + 9], 0x7632);
            l[2 * qi]     = __byte_perm(breg[2 * qi],     breg[2 * qi + 1], 0x5410);
            l[2 * qi + 1] = __byte_perm(breg[2 * qi + 8], breg[2 * qi + 9], 0x5410);
        }
        int ntile = lrow >> 3, gg = lrow & 7;
        char* base = smem + buf * CV_STAGE + (ntile * 2 + half) * 256 + gg * 32;
        *(uint4*)(base + CV_BH)      = make_uint4(h[0], h[1], h[2], h[3]);
        *(uint4*)(base + CV_BH + 16) = make_uint4(h[4], h[5], h[6], h[7]);
        *(uint4*)(base + CV_BL)      = make_uint4(l[0], l[1], l[2], l[3]);
        *(uint4*)(base + CV_BL + 16) = make_uint4(l[4], l[5], l[6], l[7]);
    };

    float acc[2][8][4];
#pragma unroll
    for (int i = 0; i < 2; i++)
#pragma unroll
        for (int j = 0; j < 8; j++)
#pragma unroll
            for (int q = 0; q < 4; q++) acc[i][j][q] = 0.f;

    int buf = 0;
    issueA(ck0, 0);
    loadB(ck0);

    for (int ck = ck0; ck < ck1; ck++) {
        storeB(buf);
        cp_wait<0>();
        __syncthreads();
        if (ck + 1 < ck1) {
            issueA(ck + 1, buf ^ 1);
            loadB(ck + 1);
        }

        const char* st = smem + buf * CV_STAGE;
#pragma unroll
        for (int kk = 0; kk < 2; kk++) {
            uint4 ah[2], al[2];
#pragma unroll
            for (int mt = 0; mt < 2; mt++) {
                int tdx = (wid >> 1) * 2 + mt;
                const char* pA = st + (tdx * 2 + kk) * 512 + lane * 16;
                ah[mt] = *(const uint4*)(pA + CV_AH);
                al[mt] = *(const uint4*)(pA + CV_AL);
            }
#pragma unroll
            for (int nt = 0; nt < 8; nt++) {
                int blk = ((wid & 1) * 8 + nt) * 2 + kk;
                const char* pB = st + blk * 256 + lane * 8;
                uint2 bh = *(const uint2*)(pB + CV_BH);
                uint2 bl = *(const uint2*)(pB + CV_BL);
                mma_bf16(acc[0][nt], (const u32*)&ah[0], bh.x, bh.y);
                mma_bf16(acc[1][nt], (const u32*)&ah[1], bh.x, bh.y);
                mma_bf16(acc[0][nt], (const u32*)&al[0], bh.x, bh.y);
                mma_bf16(acc[1][nt], (const u32*)&al[1], bh.x, bh.y);
                mma_bf16(acc[0][nt], (const u32*)&ah[0], bl.x, bl.y);
                mma_bf16(acc[1][nt], (const u32*)&ah[1], bl.x, bl.y);
            }
        }
        buf ^= 1;
    }
    __syncthreads();

    // ---- epilogue: smem-staged transpose -> coalesced n-contiguous writes
    {
        const int g = lane >> 2, qi = lane & 3;
        float* tw = (float*)smem + wid * 2176;   // 32 rows x 68 floats
#pragma unroll
        for (int mt = 0; mt < 2; mt++)
#pragma unroll
            for (int nt = 0; nt < 8; nt++)
#pragma unroll
                for (int q = 0; q < 2; q++) {
                    int ln = nt * 8 + 2 * qi + q;
                    tw[(mt * 16 + g) * 68 + ln]     = acc[mt][nt][q];
                    tw[(mt * 16 + 8 + g) * 68 + ln] = acc[mt][nt][2 + q];
                }
        __syncwarp();

        int nA = n0 + nwarp + lane;
        int nB = nA + 32;
        bool okA = nA < N, okB = nB < N;
        int ncA = okA ? nA : 0, ncB = okB ? nB : 0;
        int bA = ncA / OHW, pA = ncA - bA * OHW;
        int bB = ncB / OHW, pB = ncB - bB * OHW;
        long baseA = (long)bA * M * OHW + pA;
        long baseB = (long)bB * M * OHW + pB;
        long zoff = accum ? (long)blockIdx.z * 64 * M * OHW : 0;

        for (int r = 0; r < 32; r++) {
            int m = m0 + mwarp + r;
            if (m >= M) break;
            float bv = accum ? 0.f : bias[m];
            float vA = tw[r * 68 + lane] + bv;
            float vB = tw[r * 68 + 32 + lane] + bv;
            if (relu && !accum) { vA = fmaxf(vA, 0.f); vB = fmaxf(vB, 0.f); }
            long moff = (long)m * OHW;
            if (packout) {
                u32* outp = (u32*)outv;
                if (okA) outp[baseA + moff] = pack_hilo(vA);
                if (okB) outp[baseB + moff] = pack_hilo(vB);
            } else {
                float* outp = (float*)outv;
                if (okA) outp[zoff + baseA + moff] = vA;
                if (okB) outp[zoff + baseB + moff] = vB;
            }
        }
    }
}

// ---------------------------------------------------------------------------
// 64x64-tile f32x2 GEMM (FC layers), deterministic split-K over grid.z.
// ---------------------------------------------------------------------------
__global__ __launch_bounds__(256, 2) void gemm64_k(
    const float* __restrict__ A, const float* __restrict__ Bm,
    const float* __restrict__ bias, float* __restrict__ Cout,
    int M, int N, int K, int relu, int nsplit)
{
    __shared__ __align__(16) float As[16][64];
    __shared__ __align__(16) float Bs[16][64];

    const int tid = threadIdx.x;
    const int m0 = blockIdx.y * 64, n0 = blockIdx.x * 64;
    const int tx = tid & 15, ty = tid >> 4;
    const int lm = tid & 63;
    const int lk4 = (tid >> 6) * 4;

    const int nblk = K >> 4;
    const int base = nblk / nsplit, rem = nblk % nsplit;
    const int z = blockIdx.z;
    const int sblk = z * base + (z < rem ? z : rem);
    const int myblk = base + (z < rem ? 1 : 0);
    const int klo = sblk << 4, khi = (sblk + myblk) << 4;
    const long zoff = (long)z * M * N;

    ull acc[4][2];
#pragma unroll
    for (int i = 0; i < 4; i++) { acc[i][0] = 0ULL; acc[i][1] = 0ULL; }

    for (int k0 = klo; k0 < khi; k0 += 16) {
        {
            int gm = m0 + lm;
            if (gm < M) {
                float4 av = *(const float4*)&A[(long)gm * K + k0 + lk4];
                As[lk4 + 0][lm] = av.x; As[lk4 + 1][lm] = av.y;
                As[lk4 + 2][lm] = av.z; As[lk4 + 3][lm] = av.w;
            } else {
                As[lk4 + 0][lm] = 0.f; As[lk4 + 1][lm] = 0.f;
                As[lk4 + 2][lm] = 0.f; As[lk4 + 3][lm] = 0.f;
            }
        }
        {
            int gn = n0 + lm;
            if (gn < N) {
                float4 bv = *(const float4*)&Bm[(long)gn * K + k0 + lk4];
                Bs[lk4 + 0][lm] = bv.x; Bs[lk4 + 1][lm] = bv.y;
                Bs[lk4 + 2][lm] = bv.z; Bs[lk4 + 3][lm] = bv.w;
            } else {
                Bs[lk4 + 0][lm] = 0.f; Bs[lk4 + 1][lm] = 0.f;
                Bs[lk4 + 2][lm] = 0.f; Bs[lk4 + 3][lm] = 0.f;
            }
        }
        __syncthreads();
#pragma unroll
        for (int kk = 0; kk < 16; kk++) {
            float4 a4 = *(const float4*)&As[kk][ty * 4];
            ulonglong2 bv = *(const ulonglong2*)&Bs[kk][tx * 4];
            ull bp[2] = {bv.x, bv.y};
            float av[4] = {a4.x, a4.y, a4.z, a4.w};
#pragma unroll
            for (int i = 0; i < 4; i++) {
                ull sa;
                asm("mov.b64 %0, {%1, %1};" : "=l"(sa) : "f"(av[i]));
#pragma unroll
                for (int j = 0; j < 2; j++)
                    asm("fma.rn.f32x2 %0, %1, %2, %0;"
                        : "+l"(acc[i][j]) : "l"(sa), "l"(bp[j]));
            }
        }
        __syncthreads();
    }

#pragma unroll
    for (int i = 0; i < 4; i++) {
        int m = m0 + ty * 4 + i;
        if (m >= M) continue;
        float bv = (nsplit == 1 && bias) ? bias[m] : 0.f;
#pragma unroll
        for (int j = 0; j < 2; j++) {
            float lo, hi;
            asm("mov.b64 {%0, %1}, %2;" : "=f"(lo), "=f"(hi) : "l"(acc[i][j]));
            float v0 = lo + bv, v1 = hi + bv;
            if (relu && nsplit == 1) { if (v0 < 0.f) v0 = 0.f; if (v1 < 0.f) v1 = 0.f; }
            int nA = n0 + tx * 4 + 2 * j, nB = nA + 1;
            if (nA < N) Cout[zoff + (long)nA * M + m] = v0;
            if (nB < N) Cout[zoff + (long)nB * M + m] = v1;
        }
    }
}

// combine FC split-K partials + bias (+relu)
__global__ void fccomb_k(const float* __restrict__ part, const float* __restrict__ bias,
                         float* __restrict__ out, int M, int slice, int ns,
                         int relu, int total)
{
    int i = blockIdx.x * blockDim.x + threadIdx.x;
    if (i >= total) return;
    float s = 0.f;
    for (int z = 0; z < ns; z++) s += part[(long)z * slice + i];
    s += bias[i % M];
    if (relu && s < 0.f) s = 0.f;
    out[i] = s;
}

// ---------------------------------------------------------------------------
// Templated MaxPool (3x3 s2), packed u32 output
// ---------------------------------------------------------------------------
template<int C, int H, int W, int OH, int OW, int PAD>
__global__ void maxpool_k(const float* __restrict__ in, u32* __restrict__ out)
{
    constexpr int TOTAL = 64 * C * OH * OW;
    int idx = blockIdx.x * blockDim.x + threadIdx.x;
    if (idx >= TOTAL) return;
    int ow = idx % OW;
    int t = idx / OW;
    int oh = t % OH; t /= OH;
    int c = t % C;
    int b = t / C;
    const float* p = in + (long)(b * C + c) * H * W;
    float mx = -3.4e38f;
    int h0 = oh * 2 - PAD, w0 = ow * 2 - PAD;
#pragma unroll
    for (int kh = 0; kh < 3; kh++) {
        int ih = h0 + kh;
        if (ih < 0 || ih >= H) continue;
#pragma unroll
        for (int kw = 0; kw < 3; kw++) {
            int iw = w0 + kw;
            if (iw < 0 || iw >= W) continue;
            float v = p[ih * W + iw];
            if (v > mx) mx = v;
        }
    }
    out[idx] = pack_hilo(mx);
}

// ---------------------------------------------------------------------------
// pcfuse: split-K combine + bias + squash + transpose -> ut[i][b][8]
// ---------------------------------------------------------------------------
__global__ void pcfuse_k(const float* __restrict__ part, const float* __restrict__ bias,
                         float* __restrict__ ut)
{
    int idx = blockIdx.x * blockDim.x + threadIdx.x;   // 73728 = b*1152+i
    if (idx >= 73728) return;
    int b = idx / 1152, i = idx - b * 1152;
    long base = (long)b * 9216 + (long)i * 8;
    float vals[8];
    float sq = 0.f;
#pragma unroll
    for (int d = 0; d < 8; d++) {
        long f = base + d;
        int m = (i * 8 + d) / 36;
        float s = part[f] + part[f + 589824] + part[f + 1179648] + part[f + 1769472]
                + bias[m];
        vals[d] = s;
        sq += s * s;
    }
    float sc = (sq / (1.f + sq)) / sqrtf(sq + 1e-8f);
    float4* dst = (float4*)(ut + ((long)i * 64 + b) * 8);
    dst[0] = make_float4(vals[0] * sc, vals[1] * sc, vals[2] * sc, vals[3] * sc);
    dst[1] = make_float4(vals[4] * sc, vals[5] * sc, vals[6] * sc, vals[7] * sc);
}

// ---------------------------------------------------------------------------
// Fused routing — x_hat recomputed on the fly from W (L2-resident) + u.
// v2: 64-i chunks (grid 18x101), 32KB W smem -> 2+ CTAs/SM.
// ---------------------------------------------------------------------------
static constexpr int FR_SMEM = 8192 * 4 + 4 * 64 * 17 * 4;   // 50176
static constexpr int FU_SMEM = 8192 * 4;                     // 32768

__global__ __launch_bounds__(256) void fr_k(
    const float* __restrict__ Wc, const float* __restrict__ ut,
    const float* __restrict__ cct, const float* __restrict__ isum,
    float* __restrict__ sp)
{
    extern __shared__ float sm[];
    float* Wsm = sm;                 // 8192 floats (64 i-rows, d-major)
    float* red = sm + 8192;          // 4*64*17
    const int tid = threadIdx.x;
    const int p = blockIdx.x, j = blockIdx.y;
    const int i0 = p * 64;
    const int s = tid >> 6, b = tid & 63;

    const float* wsrc = Wc + ((long)j * 1152 + i0) * 128;
    for (int idx = tid; idx < 8192; idx += 256) {
        int row = idx >> 7, r = idx & 127;
        Wsm[row * 128 + (r & 7) * 16 + (r >> 3)] = wsrc[idx];
    }
    __syncthreads();

    ull accp[8];
#pragma unroll
    for (int op = 0; op < 8; op++) accp[op] = 0ULL;

    for (int k = 0; k < 16; k++) {
        const int il = s + 4 * k;
        const int i = i0 + il;
        const float4* up = (const float4*)(ut + ((long)i * 64 + b) * 8);
        float4 u0 = up[0], u1 = up[1];
        float ud[8] = {u0.x, u0.y, u0.z, u0.w, u1.x, u1.y, u1.z, u1.w};
        float cw;
        if (cct) cw = cct[((long)j * 1152 + i) * 64 + b] * isum[i * 64 + b];
        else     cw = 1.f / 101.f;
        const float* wr = Wsm + il * 128;
        ull xp[8];
#pragma unroll
        for (int op = 0; op < 8; op++) xp[op] = 0ULL;
#pragma unroll
        for (int d = 0; d < 8; d++) {
            ull us;
            asm("mov.b64 %0, {%1, %1};" : "=l"(us) : "f"(ud[d]));
            const ulonglong2* wp2 = (const ulonglong2*)(wr + d * 16);
#pragma unroll
            for (int q = 0; q < 4; q++) {
                ulonglong2 wv = wp2[q];
                asm("fma.rn.f32x2 %0, %1, %2, %0;" : "+l"(xp[2*q])   : "l"(us), "l"(wv.x));
                asm("fma.rn.f32x2 %0, %1, %2, %0;" : "+l"(xp[2*q+1]) : "l"(us), "l"(wv.y));
            }
        }
        ull cws;
        asm("mov.b64 %0, {%1, %1};" : "=l"(cws) : "f"(cw));
#pragma unroll
        for (int op = 0; op < 8; op++)
            asm("fma.rn.f32x2 %0, %1, %2, %0;" : "+l"(accp[op]) : "l"(cws), "l"(xp[op]));
    }

    float* rr = red + (s * 64 + b) * 17;
#pragma unroll
    for (int op = 0; op < 8; op++) {
        float lo, hi;
        asm("mov.b64 {%0, %1}, %2;" : "=f"(lo), "=f"(hi) : "l"(accp[op]));
        rr[2 * op] = lo; rr[2 * op + 1] = hi;
    }
    __syncthreads();
    for (int t = tid; t < 1024; t += 256) {
        int ob = t >> 4, oo = t & 15;
        float sum = red[(ob) * 17 + oo] + red[(64 + ob) * 17 + oo]
                  + red[(128 + ob) * 17 + oo] + red[(192 + ob) * 17 + oo];
        sp[(((long)p * 64 + ob) * 101 + j) * 16 + oo] = sum;
    }
}

// combine 18 partials + squash -> v [b][j][o]
__global__ void fs_k(const float* __restrict__ sp, float* __restrict__ vout, int total)
{
    int idx = blockIdx.x * blockDim.x + threadIdx.x;
    if (idx >= total) return;               // 103424
    float sum = 0.f;
#pragma unroll
    for (int p = 0; p < 18; p++) sum += sp[(long)p * 103424 + idx];
    float sq = sum * sum;
#pragma unroll
    for (int off = 8; off > 0; off >>= 1)
        sq += __shfl_xor_sync(0xffffffffu, sq, off, 16);
    float sc = (sq / (1.f + sq)) / sqrtf(sq + 1e-8f);
    vout[idx] = sum * sc;
}

__global__ __launch_bounds__(256) void fu_k(
    const float* __restrict__ Wc, const float* __restrict__ ut,
    const float* __restrict__ v, float* __restrict__ bl, int overwrite)
{
    extern __shared__ float sm[];
    float* Wsm = sm;                 // 8192 floats
    const int tid = threadIdx.x;
    const int p = blockIdx.x, j = blockIdx.y;
    const int i0 = p * 64;
    const int s = tid >> 6, b = tid & 63;

    const float* wsrc = Wc + ((long)j * 1152 + i0) * 128;
    for (int idx = tid; idx < 8192; idx += 256) {
        int row = idx >> 7, r = idx & 127;
        Wsm[row * 128 + (r & 7) * 16 + (r >> 3)] = wsrc[idx];
    }
    __syncthreads();

    ull vp[8];
    const ull* vptr = (const ull*)(v + ((long)b * 101 + j) * 16);
#pragma unroll
    for (int op = 0; op < 8; op++) vp[op] = vptr[op];

    for (int k = 0; k < 16; k++) {
        const int il = s + 4 * k;
        const int i = i0 + il;
        const float4* up = (const float4*)(ut + ((long)i * 64 + b) * 8);
        float4 u0 = up[0], u1 = up[1];
        float ud[8] = {u0.x, u0.y, u0.z, u0.w, u1.x, u1.y, u1.z, u1.w};
        const float* wr = Wsm + il * 128;
        ull xp[8];
#pragma unroll
        for (int op = 0; op < 8; op++) xp[op] = 0ULL;
#pragma unroll
        for (int d = 0; d < 8; d++) {
            ull us;
            asm("mov.b64 %0, {%1, %1};" : "=l"(us) : "f"(ud[d]));
            const ulonglong2* wp2 = (const ulonglong2*)(wr + d * 16);
#pragma unroll
            for (int q = 0; q < 4; q++) {
                ulonglong2 wv = wp2[q];
                asm("fma.rn.f32x2 %0, %1, %2, %0;" : "+l"(xp[2*q])   : "l"(us), "l"(wv.x));
                asm("fma.rn.f32x2 %0, %1, %2, %0;" : "+l"(xp[2*q+1]) : "l"(us), "l"(wv.y));
            }
        }
        ull dp = 0ULL;
#pragma unroll
        for (int op = 0; op < 8; op++)
            asm("fma.rn.f32x2 %0, %1, %2, %0;" : "+l"(dp) : "l"(vp[op]), "l"(xp[op]));
        float lo, hi;
        asm("mov.b64 {%0, %1}, %2;" : "=f"(lo), "=f"(hi) : "l"(dp));
        float d = lo + hi;
        long addr = ((long)j * 1152 + i) * 64 + b;
        bl[addr] = overwrite ? d : bl[addr] + d;
    }
}

// softmax over j; layout [101][1152][64]. 2-pass: unnormalized exp + 1/sum.
__global__ void softmax_t_k(const float* __restrict__ bl, float* __restrict__ cct,
                            float* __restrict__ isum, int total)
{
    int idx = blockIdx.x * blockDim.x + threadIdx.x;
    if (idx >= total) return;    // 73728
    const float* p = bl + idx;
    float mx = p[0];
    for (int j = 1; j < 101; j++) {
        float t = p[(long)j * 73728];
        if (t > mx) mx = t;
    }
    float* q = cct + idx;
    float sum = 0.f;
    for (int j = 0; j < 101; j++) {
        float e = __expf(p[(long)j * 73728] - mx);
        q[(long)j * 73728] = e;
        sum += e;
    }
    isum[idx] = 1.f / sum;
}

// ---------------------------------------------------------------------------
// Host-side orchestration
// ---------------------------------------------------------------------------
static float* symaddr(const void* sym)
{
    void* p = nullptr;
    cudaGetSymbolAddress(&p, sym);
    return (float*)p;
}

struct WReg { int Mpad, Kpad, nstage; u32 *whi, *wlo; };

static WReg wreg(u32* base, size_t off, int M, int K)
{
    WReg r;
    r.Kpad = ((K + 31) / 32) * 32;
    r.Mpad = ((M + 127) / 128) * 128;
    r.nstage = r.Kpad / 32;
    r.whi = base + off;
    r.wlo = r.whi + (size_t)r.Mpad * r.Kpad / 2;
    return r;
}

static void run_packw(const float* w, const WReg& r, int M, int K)
{
    int tot = r.Mpad * r.Kpad / 2;
    pack_wfrag_k<<<(tot + 255) / 256, 256>>>(w, r.whi, r.wlo, M, K, r.Kpad, r.nstage, tot);
}

template<int KH, int KW, int SS, int PP>
static void run_conv(const WReg& r, const u32* pin, const float* bias, void* outv,
                     int M, int C, int H, int Win, int OH, int OW, int relu,
                     int packout, int accum, int nsplit)
{
    const int K = C * KH * KW;
    static bool attr11 = false, attr5 = false, attr3 = false;
    bool& flag = (KH == 11) ? attr11 : (KH == 5) ? attr5 : attr3;
    if (!flag) {
        cudaFuncSetAttribute(convhmma_k<KH, KW, SS, PP>,
                             cudaFuncAttributeMaxDynamicSharedMemorySize, CV_SMEM);
        flag = true;
    }
    int N = 64 * OH * OW;
    dim3 grid((N + 127) / 128, r.Mpad / 128, nsplit);
    convhmma_k<KH, KW, SS, PP><<<grid, 256, CV_SMEM>>>(r.whi, r.wlo, pin, bias, outv,
                                                       M, C, H, Win, OH, OW, K, r.Kpad,
                                                       relu, packout, accum, nsplit);
}

static void run_fc(const float* A, const float* Bm, const float* bias,
                   float* part, float* Cout, int M, int N, int K, int relu, int nsplit)
{
    dim3 grid((N + 63) / 64, (M + 63) / 64, nsplit);
    if (nsplit == 1) {
        gemm64_k<<<grid, 256>>>(A, Bm, bias, Cout, M, N, K, relu, 1);
    } else {
        gemm64_k<<<grid, 256>>>(A, Bm, nullptr, part, M, N, K, 0, nsplit);
        int total = M * N;
        fccomb_k<<<(total + 255) / 256, 256>>>(part, bias, Cout, M, M * N, nsplit,
                                               relu, total);
    }
}

extern "C" void kernel_launch(void* const* d_in, const int* in_sizes, int n_in,
                              void* d_out, int out_size)
{
    const float* x      = (const float*)d_in[0];
    const float* w1     = (const float*)d_in[1];
    const float* b1     = (const float*)d_in[2];
    const float* w2     = (const float*)d_in[3];
    const float* b2     = (const float*)d_in[4];
    const float* w3     = (const float*)d_in[5];
    const float* b3     = (const float*)d_in[6];
    const float* w4     = (const float*)d_in[7];
    const float* b4     = (const float*)d_in[8];
    const float* w5     = (const float*)d_in[9];
    const float* b5     = (const float*)d_in[10];
    const float* pc_w   = (const float*)d_in[11];
    const float* pc_b   = (const float*)d_in[12];
    const float* caps_W = (const float*)d_in[13];
    const float* fc1_w  = (const float*)d_in[14];
    const float* fc1_b  = (const float*)d_in[15];
    const float* fc2_w  = (const float*)d_in[16];
    const float* fc2_b  = (const float*)d_in[17];
    const float* fc3_w  = (const float*)d_in[18];
    const float* fc3_b  = (const float*)d_in[19];
    float* out = (float*)d_out;

    float* a1  = symaddr(g_a1);
    float* a2  = symaddr(g_a2);
    float* a5  = symaddr(g_a5);
    float* pcp = symaddr(g_pcpart);
    float* ut  = symaddr(g_ut);
    float* bl  = symaddr(g_bl);
    float* cc  = symaddr(g_cc);
    float* is  = symaddr(g_isum);
    float* v   = symaddr(g_v);
    float* f1  = symaddr(g_f1);
    float* f2  = symaddr(g_f2);
    u32* bufA = (u32*)symaddr(g_packA);
    u32* bufB = (u32*)symaddr(g_packB);
    u32* pw   = (u32*)symaddr(g_packW);

    // per-layer weight regions (fragment-major, hi+lo)
    WReg r1 = wreg(pw, 0,       96,  3 * 121);
    WReg r2 = wreg(pw, 49152,   256, 96 * 25);
    WReg r3 = wreg(pw, 663552,  384, 256 * 9);
    WReg r4 = wreg(pw, 1548288, 384, 384 * 9);
    WReg r5 = wreg(pw, 2875392, 256, 384 * 9);
    WReg rp = wreg(pw, 3760128, 256, 256 * 9);

    // ---- conv stack ----
    run_packw(w1, r1, 96, 3 * 121);
    run_packw(w2, r2, 256, 96 * 25);
    {
        int tot = 64 * 3 * 227 * 227;
        pack_act_k<<<(tot + 255) / 256, 256>>>(x, bufA, tot);
    }
    run_conv<11, 11, 4, 0>(r1, bufA, b1, a1, 96, 3, 227, 227, 55, 55, 1, 0, 0, 1);
    maxpool_k<96, 55, 55, 27, 27, 0><<<(64 * 96 * 27 * 27 + 255) / 256, 256>>>(a1, bufA);

    run_conv<5, 5, 1, 2>(r2, bufA, b2, a2, 256, 96, 27, 27, 27, 27, 1, 0, 0, 1);
    maxpool_k<256, 27, 27, 14, 14, 1><<<(64 * 256 * 14 * 14 + 255) / 256, 256>>>(a2, bufA);

    run_packw(w3, r3, 384, 256 * 9);
    run_conv<3, 3, 1, 1>(r3, bufA, b3, bufB, 384, 256, 14, 14, 14, 14, 1, 1, 0, 1);
    run_packw(w4, r4, 384, 384 * 9);
    run_conv<3, 3, 1, 1>(r4, bufB, b4, bufA, 384, 384, 14, 14, 14, 14, 1, 1, 0, 1);
    run_packw(w5, r5, 256, 384 * 9);
    run_conv<3, 3, 1, 1>(r5, bufA, b5, a5, 256, 384, 14, 14, 14, 14, 1, 0, 0, 1);
    maxpool_k<256, 14, 14, 6, 6, 0><<<(64 * 256 * 6 * 6 + 255) / 256, 256>>>(a5, bufA);

    // ---- PrimaryCaps conv: split-K x4 + fused combine/squash/transpose ----
    run_packw(pc_w, rp, 256, 256 * 9);
    run_conv<3, 3, 1, 1>(rp, bufA, pc_b, pcp, 256, 256, 6, 6, 6, 6, 0, 0, 1, 4);
    pcfuse_k<<<(73728 + 255) / 256, 256>>>(pcp, pc_b, ut);

    // ---- fused dynamic routing (64-i chunks; sp partials reuse pcp) ----
    {
        static bool attrr = false;
        if (!attrr) {
            cudaFuncSetAttribute(fr_k, cudaFuncAttributeMaxDynamicSharedMemorySize, FR_SMEM);
            cudaFuncSetAttribute(fu_k, cudaFuncAttributeMaxDynamicSharedMemorySize, FU_SMEM);
            attrr = true;
        }
        dim3 rg(18, 101);
        fr_k<<<rg, 256, FR_SMEM>>>(caps_W, ut, nullptr, nullptr, pcp);
        fs_k<<<404, 256>>>(pcp, v, 103424);
        fu_k<<<rg, 256, FU_SMEM>>>(caps_W, ut, v, bl, 1);
        softmax_t_k<<<288, 256>>>(bl, cc, is, 73728);
        fr_k<<<rg, 256, FR_SMEM>>>(caps_W, ut, cc, is, pcp);
        fs_k<<<404, 256>>>(pcp, v, 103424);
        fu_k<<<rg, 256, FU_SMEM>>>(caps_W, ut, v, bl, 0);
        softmax_t_k<<<288, 256>>>(bl, cc, is, 73728);
        fr_k<<<rg, 256, FR_SMEM>>>(caps_W, ut, cc, is, pcp);
        fs_k<<<404, 256>>>(pcp, v, 103424);
    }

    // ---- MLP head (deterministic split-K, partials in pcp) ----
    run_fc(fc1_w, v, fc1_b, pcp, f1, 4096, 64, 1616, 1, 4);
    run_fc(fc2_w, f1, fc2_b, pcp, f2, 4096, 64, 4096, 1, 4);
    run_fc(fc3_w, f2, fc3_b, pcp, out, 101, 64, 4096, 0, 16);
}